// round 13
// baseline (speedup 1.0000x reference)
#include <cuda_runtime.h>
#include <cuda_bf16.h>
#include <cstdint>

#define N_NODES 50000
#define N_EDGES 400000
#define IN_C 32
#define OUT_C 32
#define EDGE_DIM 16
#define HIDDEN 128
#define BN_EPS 1e-5f

#define A_COLS (HIDDEN * IN_C)   // 4096
#define A_U32 (A_COLS / 2)       // 2048 packed u32 per node per plane
#define BN_BLOCKS 232

// GEMM tiling (both paths): 128 rows/block
#define TCM 128
#define KT2 64                    // bf16 per K tile in tcgen05 path (128B rows)
#define NK2 (A_COLS / KT2)        // 64
#define TCGRID ((N_NODES + TCM - 1) / TCM)   // 391
#define BUFSZ 40960               // A_hi 16K | A_lo 16K | W_hi 4K | W_lo 4K
#define TC_DYN (2 * BUFSZ + 1024)
#define TC_IDESC 0x8080490u       // c=F32, a/b=BF16 K-major, M=128, N=32

// fallback tiling
#define FBK 32
#define FNKT (A_COLS / FBK)       // 128
#define FASTR 40
#define FWSTR 40

// abuild: node-group blocking
#define GNODES 16
#define ECAP 128
#define NGROUPS ((N_NODES + GNODES - 1) / GNODES)   // 3125

// tcgen05 availability: only in arch-specific ('a') device passes
#if defined(__CUDA_ARCH__) && (defined(__CUDA_ARCH_FEAT_SM103_ALL) || \
    defined(__CUDA_ARCH_FEAT_SM100_ALL) || defined(__CUDA_ARCH_FEAT_SM101_ALL) || \
    defined(__CUDA_ARCH_SPECIFIC__))
#define HAS_TC 1
#else
#define HAS_TC 0
#endif

// ---------------- static device scratch (no allocations allowed) ------------
__device__ uint32_t g_Ah[(size_t)N_NODES * A_U32];     // 410 MB (bf16 hi pairs)
__device__ uint32_t g_Al[(size_t)N_NODES * A_U32];     // 410 MB (bf16 lo pairs)
__device__ uint32_t g_w2h[128 * 512];                  // W2 hi plane [kt32][n][kp]
__device__ uint32_t g_w2l[128 * 512];
__device__ float g_xsum[(size_t)N_NODES * IN_C];
__device__ float g_h[(size_t)N_NODES * OUT_C];
__device__ int   g_hist[N_NODES];   // zero at module load; re-zeroed by k_scan
__device__ int   g_off[N_NODES + 1];
__device__ int   g_cursor[N_NODES];
__device__ int   g_perm[N_EDGES];
__device__ double g_psum[BN_BLOCKS][OUT_C];
__device__ double g_psq[BN_BLOCKS][OUT_C];
__device__ float g_scale[OUT_C];
__device__ float g_shift[OUT_C];

// ---------------- helpers ----------------------------------------------------
__device__ __forceinline__ void split_bf(float v, __nv_bfloat16& h,
                                         __nv_bfloat16& l) {
    h = __float2bfloat16_rn(v);
    l = __float2bfloat16_rn(v - __bfloat162float(h));
}

__device__ __forceinline__ uint32_t pack_bf(__nv_bfloat16 a, __nv_bfloat16 b) {
    __nv_bfloat162 p;
    p.x = a; p.y = b;
    return *reinterpret_cast<uint32_t*>(&p);
}

__device__ __forceinline__ uint32_t lds_u32(const __nv_bfloat16* p) {
    return *reinterpret_cast<const uint32_t*>(p);
}

__device__ __forceinline__ void mma16816(float c[4], uint32_t a0, uint32_t a1,
                                         uint32_t a2, uint32_t a3, uint32_t b0,
                                         uint32_t b1) {
    asm volatile(
        "mma.sync.aligned.m16n8k16.row.col.f32.bf16.bf16.f32 "
        "{%0,%1,%2,%3}, {%4,%5,%6,%7}, {%8,%9}, {%0,%1,%2,%3};"
        : "+f"(c[0]), "+f"(c[1]), "+f"(c[2]), "+f"(c[3])
        : "r"(a0), "r"(a1), "r"(a2), "r"(a3), "r"(b0), "r"(b1));
}

// packed f32x2 ops (sm_100+)
__device__ __forceinline__ unsigned long long pack2(float a, float b) {
    unsigned long long r;
    asm("mov.b64 %0, {%1, %2};" : "=l"(r) : "f"(a), "f"(b));
    return r;
}
__device__ __forceinline__ void unpack2(unsigned long long v, float& a, float& b) {
    asm("mov.b64 {%0, %1}, %2;" : "=f"(a), "=f"(b) : "l"(v));
}
__device__ __forceinline__ void fma2(unsigned long long& d, unsigned long long a,
                                     unsigned long long b) {
    asm("fma.rn.f32x2 %0, %1, %2, %0;" : "+l"(d) : "l"(a), "l"(b));
}
__device__ __forceinline__ unsigned long long mul2(unsigned long long a,
                                                   unsigned long long b) {
    unsigned long long r;
    asm("mul.rn.f32x2 %0, %1, %2;" : "=l"(r) : "l"(a), "l"(b));
    return r;
}

// self-detecting edge-index load (int32 vs int64 buffer layout)
__device__ __forceinline__ int detect64(const void* ei) {
    const int* p = (const int*)ei;
    return (p[1] == 0) & (p[3] == 0) & (p[5] == 0) & (p[7] == 0);
}
__device__ __forceinline__ int load_idx(const void* ei, int is64, long long elem) {
    int v = is64 ? (int)((const long long*)ei)[elem] : ((const int*)ei)[elem];
    return min(max(v, 0), N_NODES - 1);
}

// ---------------- smem/mbarrier primitives (arch-neutral) --------------------
__device__ __forceinline__ uint32_t smem_u32(const void* p) {
    uint32_t a;
    asm("{ .reg .u64 t; cvta.to.shared.u64 t, %1; cvt.u32.u64 %0, t; }"
        : "=r"(a) : "l"(p));
    return a;
}
__device__ __forceinline__ uint32_t swz128(uint32_t off) {
    return off ^ ((off >> 3) & 0x70);
}

#if HAS_TC
__device__ __forceinline__ uint32_t elect_one() {
    uint32_t pred;
    asm volatile("{\n\t.reg .pred p;\n\telect.sync _|p, 0xFFFFFFFF;\n\t"
                 "selp.b32 %0, 1, 0, p;\n\t}" : "=r"(pred));
    return pred;
}
__device__ __forceinline__ void mbar_init(uint32_t a, uint32_t c) {
    asm volatile("mbarrier.init.shared.b64 [%0], %1;" :: "r"(a), "r"(c) : "memory");
}
__device__ __forceinline__ void mbar_wait(uint32_t a, uint32_t par) {
    asm volatile(
        "{\n\t.reg .pred P;\n\t"
        "WL%=:\n\t"
        "mbarrier.try_wait.parity.acquire.cta.shared::cta.b64 P, [%0], %1;\n\t"
        "@!P bra WL%=;\n\t}"
        :: "r"(a), "r"(par) : "memory");
}
__device__ __forceinline__ void tc_alloc(uint32_t slot, uint32_t ncols) {
    asm volatile("tcgen05.alloc.cta_group::1.sync.aligned.shared::cta.b32 [%0], %1;"
                 :: "r"(slot), "r"(ncols) : "memory");
}
__device__ __forceinline__ void tc_relinq() {
    asm volatile("tcgen05.relinquish_alloc_permit.cta_group::1.sync.aligned;");
}
__device__ __forceinline__ void tc_dealloc(uint32_t base, uint32_t ncols) {
    asm volatile("tcgen05.dealloc.cta_group::1.sync.aligned.b32 %0, %1;"
                 :: "r"(base), "r"(ncols));
}
__device__ __forceinline__ void tc_commit(uint32_t mbar) {
    asm volatile(
        "tcgen05.commit.cta_group::1.mbarrier::arrive::one.shared::cluster.b64 [%0];"
        :: "r"(mbar) : "memory");
}
__device__ __forceinline__ void tc_fence_after() {
    asm volatile("tcgen05.fence::after_thread_sync;" ::: "memory");
}
__device__ __forceinline__ void fence_async_shared() {
    asm volatile("fence.proxy.async.shared::cta;" ::: "memory");
}
__device__ __forceinline__ void tc_mma_f16_ss(uint32_t d, uint64_t a, uint64_t b,
                                              uint32_t idesc, bool acc) {
    uint32_t en = acc ? 1u : 0u;
    asm volatile(
        "{\n\t.reg .pred p;\n\tsetp.ne.u32 p, %5, 0;\n\t"
        "tcgen05.mma.cta_group::1.kind::f16 [%0], %1, %2, %3, {%4, %4, %4, %4}, p;\n\t}"
        :: "r"(d), "l"(a), "l"(b), "r"(idesc), "r"(0u), "r"(en) : "memory");
}
__device__ __forceinline__ void tc_ld32(uint32_t* r, uint32_t addr) {
    asm volatile(
        "tcgen05.ld.sync.aligned.32x32b.x32.b32 "
        "{%0,%1,%2,%3,%4,%5,%6,%7,%8,%9,%10,%11,%12,%13,%14,%15,"
        "%16,%17,%18,%19,%20,%21,%22,%23,%24,%25,%26,%27,%28,%29,%30,%31}, [%32];"
        : "=r"(r[0]), "=r"(r[1]), "=r"(r[2]), "=r"(r[3]), "=r"(r[4]), "=r"(r[5]),
          "=r"(r[6]), "=r"(r[7]), "=r"(r[8]), "=r"(r[9]), "=r"(r[10]), "=r"(r[11]),
          "=r"(r[12]), "=r"(r[13]), "=r"(r[14]), "=r"(r[15]), "=r"(r[16]),
          "=r"(r[17]), "=r"(r[18]), "=r"(r[19]), "=r"(r[20]), "=r"(r[21]),
          "=r"(r[22]), "=r"(r[23]), "=r"(r[24]), "=r"(r[25]), "=r"(r[26]),
          "=r"(r[27]), "=r"(r[28]), "=r"(r[29]), "=r"(r[30]), "=r"(r[31])
        : "r"(addr));
}
__device__ __forceinline__ void tc_wait_ld() {
    asm volatile("tcgen05.wait::ld.sync.aligned;" ::: "memory");
}
// SW128 K-major descriptor (version=1, LBO=1, SBO=64)
__device__ __forceinline__ uint64_t mk_desc(uint32_t base) {
    return ((uint64_t)2 << 61) | ((uint64_t)1 << 46) | ((uint64_t)64 << 32) |
           ((uint64_t)1 << 16) | ((uint64_t)(base >> 4) & 0x3FFF);
}
#endif  // HAS_TC

// ---------------- launch 1: histogram over dst + W2 pre-split ----------------
__global__ void k_hist(const void* __restrict__ ei, const float* __restrict__ w2) {
    int is64 = detect64(ei);
    for (int i = blockIdx.x * blockDim.x + threadIdx.x; i < N_EDGES;
         i += gridDim.x * blockDim.x) {
        int dst = load_idx(ei, is64, (long long)N_EDGES + i);
        atomicAdd(&g_hist[dst], 1);
    }
    for (int id = blockIdx.x * blockDim.x + threadIdx.x; id < 128 * 512;
         id += gridDim.x * blockDim.x) {
        int kt = id >> 9, r = id & 511;
        int n = r >> 4, kp = r & 15;
        int k0 = kt * 32 + 2 * kp;
        float v0 = w2[(size_t)k0 * 32 + n];
        float v1 = w2[(size_t)(k0 + 1) * 32 + n];
        __nv_bfloat16 h0, l0, h1, l1;
        split_bf(v0, h0, l0);
        split_bf(v1, h1, l1);
        g_w2h[id] = pack_bf(h0, h1);
        g_w2l[id] = pack_bf(l0, l1);
    }
}

// ---------------- launch 2: single-block scan (also re-zeros g_hist) --------
__device__ __forceinline__ int block_excl_scan1024(int v, int* ws) {
    int tid = threadIdx.x;
    int lane = tid & 31, wid = tid >> 5;
    int incl = v;
#pragma unroll
    for (int o = 1; o < 32; o <<= 1) {
        int nv = __shfl_up_sync(0xffffffffu, incl, o);
        if (lane >= o) incl += nv;
    }
    if (lane == 31) ws[wid] = incl;
    __syncthreads();
    if (wid == 0) {
        int wv = ws[lane];
#pragma unroll
        for (int o = 1; o < 32; o <<= 1) {
            int nv = __shfl_up_sync(0xffffffffu, wv, o);
            if (lane >= o) wv += nv;
        }
        ws[lane] = wv;
    }
    __syncthreads();
    int base = (wid > 0) ? ws[wid - 1] : 0;
    return base + incl - v;
}

__global__ void __launch_bounds__(1024) k_scan() {
    __shared__ int ws[32];
    __shared__ int s_carry;
    int tid = threadIdx.x;
    if (tid == 0) s_carry = 0;
    __syncthreads();
    for (int base = 0; base < N_NODES; base += 1024) {
        int idx = base + tid;
        int v = (idx < N_NODES) ? g_hist[idx] : 0;
        int ex = block_excl_scan1024(v, ws);
        int c = s_carry;
        if (idx < N_NODES) {
            g_off[idx] = c + ex;
            g_cursor[idx] = c + ex;
            g_hist[idx] = 0;
        }
        __syncthreads();
        if (tid == 1023) s_carry = c + ex + v;
        __syncthreads();
    }
    if (tid == 0) g_off[N_NODES] = N_EDGES;
}

// ---------------- launch 3: scatter edge ids grouped by dst -----------------
__global__ void k_scatter(const void* __restrict__ ei) {
    int is64 = detect64(ei);
    for (int i = blockIdx.x * blockDim.x + threadIdx.x; i < N_EDGES;
         i += gridDim.x * blockDim.x) {
        int dst = load_idx(ei, is64, (long long)N_EDGES + i);
        int pos = atomicAdd(&g_cursor[dst], 1);
        g_perm[pos] = i;
    }
}

// ---------------- launch 4 (PROFILED): A build (R11 exact) ------------------
__device__ __forceinline__ void stage_edges(int estart, int cnt, int tid,
                                            int is64, const void* ei,
                                            const float* ea, const float* x,
                                            int* s_e, int* s_src,
                                            float4 (*s_ea)[4],
                                            float4 (*s_xj)[8]) {
    __syncthreads();
    for (int j = tid; j < cnt; j += 128) {
        int e = g_perm[estart + j];
        s_e[j] = e;
        s_src[j] = load_idx(ei, is64, e);
    }
    __syncthreads();
    for (int idx = tid; idx < cnt * 4; idx += 128) {
        int j = idx >> 2, q = idx & 3;
        s_ea[j][q] = ((const float4*)(ea + (size_t)s_e[j] * EDGE_DIM))[q];
    }
    for (int idx = tid; idx < cnt * 8; idx += 128) {
        int j = idx >> 3, q = idx & 7;
        s_xj[j][q] = ((const float4*)(x + (size_t)s_src[j] * IN_C))[q];
    }
    __syncthreads();
}

__device__ __forceinline__ void accum_edge(int j, int tid,
                                           const unsigned long long* w1r2,
                                           float b1v,
                                           unsigned long long* acc2, float& xs,
                                           float4 (*s_ea)[4],
                                           float4 (*s_xj)[8]) {
    float4 e0 = s_ea[j][0], e1 = s_ea[j][1], e2 = s_ea[j][2], e3 = s_ea[j][3];
    unsigned long long h2a = mul2(pack2(e0.x, e0.y), w1r2[0]);
    unsigned long long h2b = mul2(pack2(e0.z, e0.w), w1r2[1]);
    fma2(h2a, pack2(e1.x, e1.y), w1r2[2]);
    fma2(h2b, pack2(e1.z, e1.w), w1r2[3]);
    fma2(h2a, pack2(e2.x, e2.y), w1r2[4]);
    fma2(h2b, pack2(e2.z, e2.w), w1r2[5]);
    fma2(h2a, pack2(e3.x, e3.y), w1r2[6]);
    fma2(h2b, pack2(e3.z, e3.w), w1r2[7]);
    float alo, ahi, blo, bhi;
    unpack2(h2a, alo, ahi);
    unpack2(h2b, blo, bhi);
    float he = fmaxf((alo + blo) + (ahi + bhi) + b1v, 0.f);
    unsigned long long he2 = pack2(he, he);
#pragma unroll
    for (int q = 0; q < 8; q++) {
        float4 xv = s_xj[j][q];
        fma2(acc2[2 * q], he2, pack2(xv.x, xv.y));
        fma2(acc2[2 * q + 1], he2, pack2(xv.z, xv.w));
    }
    if (tid < IN_C) xs += ((const float*)s_xj)[j * 32 + tid];
}

__device__ __forceinline__ void store_node(int n, int tid,
                                           const unsigned long long* acc2,
                                           float xs) {
    uint32_t ph[16], pl[16];
#pragma unroll
    for (int m = 0; m < 16; m++) {
        float a0, a1;
        unpack2(acc2[m], a0, a1);
        __nv_bfloat16 h0, l0, h1, l1;
        split_bf(a0, h0, l0);
        split_bf(a1, h1, l1);
        ph[m] = pack_bf(h0, h1);
        pl[m] = pack_bf(l0, l1);
    }
    uint4* aph = (uint4*)(g_Ah + (size_t)n * A_U32 + tid * 16);
    uint4* apl = (uint4*)(g_Al + (size_t)n * A_U32 + tid * 16);
#pragma unroll
    for (int q = 0; q < 4; q++) {
        aph[q] = make_uint4(ph[4 * q], ph[4 * q + 1], ph[4 * q + 2], ph[4 * q + 3]);
        apl[q] = make_uint4(pl[4 * q], pl[4 * q + 1], pl[4 * q + 2], pl[4 * q + 3]);
    }
    if (tid < IN_C) g_xsum[n * IN_C + tid] = xs;
}

__global__ void __launch_bounds__(128, 6) k_abuild(const float* __restrict__ x,
                                                   const void* __restrict__ ei,
                                                   const float* __restrict__ ea,
                                                   const float* __restrict__ w1,
                                                   const float* __restrict__ b1) {
    int tid = threadIdx.x;
    int is64 = detect64(ei);
    int n0 = blockIdx.x * GNODES;
    int nlocal = min(GNODES, N_NODES - n0);

    unsigned long long w1r2[8];
#pragma unroll
    for (int k = 0; k < 8; k++)
        w1r2[k] = pack2(w1[(2 * k) * HIDDEN + tid], w1[(2 * k + 1) * HIDDEN + tid]);
    float b1v = b1[tid];

    __shared__ int s_off[GNODES + 1];
    __shared__ int s_src[ECAP];
    __shared__ int s_e[ECAP];
    __shared__ __align__(16) float4 s_ea[ECAP][4];
    __shared__ __align__(16) float4 s_xj[ECAP][8];

    if (tid <= nlocal) s_off[tid] = g_off[n0 + tid];
    __syncthreads();

    int pnode = 0;
    while (pnode < nlocal) {
        int estart = s_off[pnode];
        int qnode = pnode;
        while (qnode < nlocal && s_off[qnode + 1] - estart <= ECAP) qnode++;

        if (qnode > pnode) {
            int cnt = s_off[qnode] - estart;
            stage_edges(estart, cnt, tid, is64, ei, ea, x, s_e, s_src, s_ea, s_xj);
            for (int nn = pnode; nn < qnode; nn++) {
                unsigned long long acc2[16];
#pragma unroll
                for (int m = 0; m < 16; m++) acc2[m] = 0ull;
                float xs = 0.f;
                int ls = s_off[nn] - estart, le = s_off[nn + 1] - estart;
                for (int j = ls; j < le; j++)
                    accum_edge(j, tid, w1r2, b1v, acc2, xs, s_ea, s_xj);
                store_node(n0 + nn, tid, acc2, xs);
            }
            pnode = qnode;
        } else {
            int d = s_off[pnode + 1] - estart;
            unsigned long long acc2[16];
#pragma unroll
            for (int m = 0; m < 16; m++) acc2[m] = 0ull;
            float xs = 0.f;
            for (int b = 0; b < d; b += ECAP) {
                int cc = min(d - b, ECAP);
                stage_edges(estart + b, cc, tid, is64, ei, ea, x, s_e, s_src,
                            s_ea, s_xj);
                for (int j = 0; j < cc; j++)
                    accum_edge(j, tid, w1r2, b1v, acc2, xs, s_ea, s_xj);
            }
            store_node(n0 + pnode, tid, acc2, xs);
            pnode++;
        }
    }
}

// ---------------- launch 5: GEMM — tcgen05 on 'a' targets, HMMA otherwise ---
__global__ void __launch_bounds__(128) k_gemm_main(const float* __restrict__ x,
                                                   const float* __restrict__ b2,
                                                   const float* __restrict__ rw,
                                                   const float* __restrict__ cb) {
    extern __shared__ __align__(16) char DYN[];
    int tid = threadIdx.x;
    int wid = tid >> 5, lane = tid & 31;
    int rowbase = blockIdx.x * TCM;

#if HAS_TC
    // ======================= tcgen05 path ===================================
    __shared__ __align__(8) unsigned long long s_mb[2];
    __shared__ uint32_t s_tmem[1];

    uint32_t dynbase = smem_u32(DYN);
    uint32_t base = (dynbase + 1023u) & ~1023u;   // SW128 needs 1024-aligned
    char* AB = DYN + (base - dynbase);

    uint32_t mb0 = smem_u32(&s_mb[0]);
    uint32_t mb1 = smem_u32(&s_mb[1]);

    if (tid == 0) {
        mbar_init(mb0, 1);
        mbar_init(mb1, 1);
    }
    if (wid == 0) {
        tc_alloc(smem_u32(&s_tmem[0]), 32);
        tc_relinq();
    }
    __syncthreads();
    uint32_t tmem_d = s_tmem[0];

    uint32_t ph0 = 0, ph1 = 0;

    for (int kt = 0; kt < NK2; kt++) {
        int b = kt & 1;
        uint32_t bufu = base + b * BUFSZ;
        char* buf = AB + b * BUFSZ;

        if (kt >= 2) {
            if (b == 0) { mbar_wait(mb0, ph0); ph0 ^= 1; }
            else        { mbar_wait(mb1, ph1); ph1 ^= 1; }
        }
        __syncthreads();

        // stage A_hi / A_lo: 128 rows x 128B, SW128
#pragma unroll
        for (int t = 0; t < 8; t++) {
            int idx = tid + t * 128;
            int row = idx >> 3, q = idx & 7;
            int mg = rowbase + row;
            uint4 vh = make_uint4(0, 0, 0, 0), vl = make_uint4(0, 0, 0, 0);
            if (mg < N_NODES) {
                vh = ((const uint4*)(g_Ah + (size_t)mg * A_U32 + kt * 32))[q];
                vl = ((const uint4*)(g_Al + (size_t)mg * A_U32 + kt * 32))[q];
            }
            uint32_t off = swz128((uint32_t)(row * 128 + q * 16));
            *(uint4*)(buf + off) = vh;
            *(uint4*)(buf + 16384 + off) = vl;
        }
        // stage W_hi / W_lo: 32 rows x 128B, SW128
#pragma unroll
        for (int t = 0; t < 2; t++) {
            int idx = tid + t * 128;
            int n = idx >> 3, g = idx & 7;
            int chunk = kt * 2 + (g >> 2);
            int src = chunk * 512 + n * 16 + (g & 3) * 4;
            uint4 vh = *(const uint4*)(g_w2h + src);
            uint4 vl = *(const uint4*)(g_w2l + src);
            uint32_t off = swz128((uint32_t)(n * 128 + g * 16));
            *(uint4*)(buf + 32768 + off) = vh;
            *(uint4*)(buf + 36864 + off) = vl;
        }
        fence_async_shared();
        __syncthreads();

        if (wid == 0 && elect_one()) {
            uint64_t dAh = mk_desc(bufu);
            uint64_t dAl = mk_desc(bufu + 16384);
            uint64_t dWh = mk_desc(bufu + 32768);
            uint64_t dWl = mk_desc(bufu + 36864);
#pragma unroll
            for (int s = 0; s < 4; s++) {
                tc_mma_f16_ss(tmem_d, dAh + 2 * s, dWh + 2 * s, TC_IDESC,
                              !(kt == 0 && s == 0));
                tc_mma_f16_ss(tmem_d, dAh + 2 * s, dWl + 2 * s, TC_IDESC, true);
                tc_mma_f16_ss(tmem_d, dAl + 2 * s, dWh + 2 * s, TC_IDESC, true);
            }
            tc_commit(b == 0 ? mb0 : mb1);
        }
    }

    mbar_wait(mb0, ph0);
    mbar_wait(mb1, ph1);
    tc_fence_after();
    __syncthreads();

    float* B2s = (float*)AB;
    float* RWs = (float*)(AB + 4096);
    float* cbs = (float*)(AB + 8192);
    for (int t = tid; t < 1024; t += 128) {
        B2s[t] = b2[t];
        RWs[t] = rw[t];
    }
    if (tid < 32) cbs[tid] = cb[tid];
    __syncthreads();

    uint32_t dreg[32];
    tc_ld32(dreg, tmem_d);
    tc_wait_ld();

    int mg = rowbase + wid * 32 + lane;
    if (mg < N_NODES) {
        float cnt = (float)(g_off[mg + 1] - g_off[mg]);
        float inv = 1.f / fmaxf(cnt, 1.f);
        float xr[32], xsr[32];
        const float4* xp = (const float4*)(x + (size_t)mg * IN_C);
        const float4* xsp = (const float4*)(g_xsum + (size_t)mg * IN_C);
#pragma unroll
        for (int q = 0; q < 8; q++) {
            float4 v = xp[q];
            xr[4 * q] = v.x; xr[4 * q + 1] = v.y;
            xr[4 * q + 2] = v.z; xr[4 * q + 3] = v.w;
            float4 s = xsp[q];
            xsr[4 * q] = s.x; xsr[4 * q + 1] = s.y;
            xsr[4 * q + 2] = s.z; xsr[4 * q + 3] = s.w;
        }
#pragma unroll 4
        for (int col = 0; col < 32; col++) {
            float e = 0.f, r = 0.f;
#pragma unroll
            for (int i = 0; i < 32; i++) {
                e += xsr[i] * B2s[i * 32 + col];
                r += xr[i] * RWs[i * 32 + col];
            }
            g_h[(size_t)mg * 32 + col] =
                (__uint_as_float(dreg[col]) + e) * inv + r + cbs[col];
        }
    }

    __syncthreads();
    if (wid == 0) tc_dealloc(tmem_d, 32);

#else
    // ======================= mma.sync fallback ==============================
    __nv_bfloat16* A_hi = (__nv_bfloat16*)DYN;               // 10240 B
    __nv_bfloat16* A_lo = (__nv_bfloat16*)(DYN + 10240);     // 10240 B
    __nv_bfloat16* Wt_hi = (__nv_bfloat16*)(DYN + 20480);    // 2560 B
    __nv_bfloat16* Wt_lo = (__nv_bfloat16*)(DYN + 23040);    // 2560 B
    float* C_s = (float*)DYN;            // 16 KB alias after the loop
    float* B2s = (float*)(DYN + 16384);
    float* RWs = (float*)(DYN + 20480 + 5120);  // after Wt planes are dead
    float* cbs = (float*)(DYN + 29696);

    int gi = lane >> 2, tq = lane & 3;
    int rb = wid * 32;

    float c[2][4][4];
#pragma unroll
    for (int rr = 0; rr < 2; rr++)
#pragma unroll
        for (int j = 0; j < 4; j++)
#pragma unroll
            for (int r = 0; r < 4; r++) c[rr][j][r] = 0.f;

    int mgrow = rowbase + tid;
    bool rowok = mgrow < N_NODES;

    for (int kt = 0; kt < FNKT; kt++) {
        // stage A (row = tid): 4 uint4 per plane
#pragma unroll
        for (int q = 0; q < 4; q++) {
            uint4 vh = rowok
                ? ((const uint4*)(g_Ah + (size_t)mgrow * A_U32))[kt * 4 + q]
                : make_uint4(0, 0, 0, 0);
            uint4 vl = rowok
                ? ((const uint4*)(g_Al + (size_t)mgrow * A_U32))[kt * 4 + q]
                : make_uint4(0, 0, 0, 0);
            ((uint4*)((uint32_t*)A_hi + tid * 20))[q] = vh;
            ((uint4*)((uint32_t*)A_lo + tid * 20))[q] = vl;
        }
        // stage W
#pragma unroll
        for (int q = 0; q < 4; q++) {
            int id = tid + q * 128;
            int n = id >> 4, kp = id & 15;
            ((uint32_t*)Wt_hi)[n * 20 + kp] = g_w2h[kt * 512 + id];
            ((uint32_t*)Wt_lo)[n * 20 + kp] = g_w2l[kt * 512 + id];
        }
        __syncthreads();

#pragma unroll
        for (int rr = 0; rr < 2; rr++) {
            int arow = rb + rr * 16 + gi;
#pragma unroll
            for (int kk = 0; kk < FBK; kk += 16) {
                const __nv_bfloat16* ah = &A_hi[arow * FASTR + kk + 2 * tq];
                const __nv_bfloat16* al = &A_lo[arow * FASTR + kk + 2 * tq];
                uint32_t a0h = lds_u32(ah), a1h = lds_u32(ah + 8 * FASTR);
                uint32_t a2h = lds_u32(ah + 8), a3h = lds_u32(ah + 8 * FASTR + 8);
                uint32_t a0l = lds_u32(al), a1l = lds_u32(al + 8 * FASTR);
                uint32_t a2l = lds_u32(al + 8), a3l = lds_u32(al + 8 * FASTR + 8);
#pragma unroll
                for (int j = 0; j < 4; j++) {
                    const __nv_bfloat16* bh =
                        &Wt_hi[(j * 8 + gi) * FWSTR + kk + 2 * tq];
                    const __nv_bfloat16* bl =
                        &Wt_lo[(j * 8 + gi) * FWSTR + kk + 2 * tq];
                    uint32_t b0h = lds_u32(bh), b1h = lds_u32(bh + 8);
                    uint32_t b0l = lds_u32(bl), b1l = lds_u32(bl + 8);
                    mma16816(c[rr][j], a0h, a1h, a2h, a3h, b0h, b1h);
                    mma16816(c[rr][j], a0h, a1h, a2h, a3h, b0l, b1l);
                    mma16816(c[rr][j], a0l, a1l, a2l, a3l, b0h, b1h);
                }
            }
        }
        __syncthreads();
    }

    // dump accumulators
#pragma unroll
    for (int rr = 0; rr < 2; rr++) {
        int row = rb + rr * 16 + gi;
#pragma unroll
        for (int j = 0; j < 4; j++) {
            int col = j * 8 + 2 * tq;
            C_s[row * 32 + col] = c[rr][j][0];
            C_s[row * 32 + col + 1] = c[rr][j][1];
            C_s[(row + 8) * 32 + col] = c[rr][j][2];
            C_s[(row + 8) * 32 + col + 1] = c[rr][j][3];
        }
    }
    __syncthreads();
    for (int t = tid; t < 1024; t += 128) {
        B2s[t] = b2[t];
        RWs[t] = rw[t];
    }
    if (tid < 32) cbs[tid] = cb[tid];
    __syncthreads();

    if (rowok) {
        float cnt = (float)(g_off[mgrow + 1] - g_off[mgrow]);
        float inv = 1.f / fmaxf(cnt, 1.f);
        float xr[32], xsr[32];
        const float4* xp = (const float4*)(x + (size_t)mgrow * IN_C);
        const float4* xsp = (const float4*)(g_xsum + (size_t)mgrow * IN_C);
#pragma unroll
        for (int q = 0; q < 8; q++) {
            float4 v = xp[q];
            xr[4 * q] = v.x; xr[4 * q + 1] = v.y;
            xr[4 * q + 2] = v.z; xr[4 * q + 3] = v.w;
            float4 s = xsp[q];
            xsr[4 * q] = s.x; xsr[4 * q + 1] = s.y;
            xsr[4 * q + 2] = s.z; xsr[4 * q + 3] = s.w;
        }
#pragma unroll 4
        for (int col = 0; col < 32; col++) {
            float e = 0.f, r = 0.f;
#pragma unroll
            for (int i = 0; i < 32; i++) {
                e += xsr[i] * B2s[i * 32 + col];
                r += xr[i] * RWs[i * 32 + col];
            }
            g_h[(size_t)mgrow * 32 + col] =
                (C_s[tid * 32 + col] + e) * inv + r + cbs[col];
        }
    }
#endif
}

// ---------------- BatchNorm statistics (deterministic, no atomics) ----------
__global__ void k_bnstats() {
    int tid = threadIdx.x;  // 256
    int c = tid & 31, g = tid >> 5;
    double s = 0.0, s2 = 0.0;
    for (int row = blockIdx.x * 8 + g; row < N_NODES; row += gridDim.x * 8) {
        float v = g_h[(size_t)row * 32 + c];
        s += (double)v;
        s2 += (double)v * (double)v;
    }
    __shared__ double sh[256], sh2[256];
    sh[tid] = s; sh2[tid] = s2;
    __syncthreads();
    for (int off = 128; off >= 32; off >>= 1) {
        if (tid < off) { sh[tid] += sh[tid + off]; sh2[tid] += sh2[tid + off]; }
        __syncthreads();
    }
    if (tid < 32) {
        g_psum[blockIdx.x][tid] = sh[tid];
        g_psq[blockIdx.x][tid] = sh2[tid];
    }
}

__global__ void k_bnfin(const float* __restrict__ gamma,
                        const float* __restrict__ beta) {
    int c = threadIdx.x;
    if (c < OUT_C) {
        double s = 0.0, s2 = 0.0;
        for (int b = 0; b < BN_BLOCKS; b++) {
            s += g_psum[b][c];
            s2 += g_psq[b][c];
        }
        double mu = s / (double)N_NODES;
        double var = s2 / (double)N_NODES - mu * mu;
        float rstd = (float)rsqrt(var + (double)BN_EPS);
        float sc = rstd * gamma[c];
        g_scale[c] = sc;
        g_shift[c] = beta[c] - (float)mu * sc;
    }
}

// ---------------- output: x + relu(BN(h)) ------------------------------------
__global__ void k_out(const float* __restrict__ x, float* __restrict__ out) {
    int i = blockIdx.x * blockDim.x + threadIdx.x;
    const int total = N_NODES * OUT_C / 4;
    if (i < total) {
        float4 xv = ((const float4*)x)[i];
        float4 hv = ((const float4*)g_h)[i];
        int c = (i & 7) * 4;
        float4 o;
        o.x = xv.x + fmaxf(hv.x * g_scale[c + 0] + g_shift[c + 0], 0.f);
        o.y = xv.y + fmaxf(hv.y * g_scale[c + 1] + g_shift[c + 1], 0.f);
        o.z = xv.z + fmaxf(hv.z * g_scale[c + 2] + g_shift[c + 2], 0.f);
        o.w = xv.w + fmaxf(hv.w * g_scale[c + 3] + g_shift[c + 3], 0.f);
        ((float4*)out)[i] = o;
    }
}

// ---------------- launch -----------------------------------------------------
extern "C" void kernel_launch(void* const* d_in, const int* in_sizes, int n_in,
                              void* d_out, int out_size) {
    const float* x   = (const float*)d_in[0];
    const void*  ei  = d_in[1];               // int32 or int64, self-detected
    const float* ea  = (const float*)d_in[2];
    const float* w1  = (const float*)d_in[3];
    const float* b1  = (const float*)d_in[4];
    const float* w2  = (const float*)d_in[5];
    const float* b2  = (const float*)d_in[6];
    const float* rw  = (const float*)d_in[7];
    const float* cb  = (const float*)d_in[8];
    const float* gam = (const float*)d_in[9];
    const float* bet = (const float*)d_in[10];
    float* out = (float*)d_out;

    cudaFuncSetAttribute(k_gemm_main, cudaFuncAttributeMaxDynamicSharedMemorySize,
                         TC_DYN);

    k_hist<<<512, 256>>>(ei, w2);             // launch 1
    k_scan<<<1, 1024>>>();                    // launch 2
    k_scatter<<<512, 256>>>(ei);              // launch 3
    k_abuild<<<NGROUPS, 128>>>(x, ei, ea, w1, b1);   // launch 4 (profiled)
    k_gemm_main<<<TCGRID, 128, TC_DYN>>>(x, b2, rw, cb);
    k_bnstats<<<BN_BLOCKS, 256>>>();
    k_bnfin<<<1, 32>>>(gam, bet);
    k_out<<<(N_NODES * OUT_C / 4 + 255) / 256, 256>>>(x, out);
}